// round 13
// baseline (speedup 1.0000x reference)
#include <cuda_runtime.h>
#include <cuda_fp16.h>
#include <math.h>
#include <stdint.h>

#define BT    16384
#define DDIM  4096
#define NCOLS 320
#define EPSF  1.1920929e-07f
#define BSCALE 64.0f
#define INVBS  0.015625f

#define BM  64
#define BK  32
#define KIT (DDIM / BK)

// smem per stage: A 64 rows x 64B (fp16) = 4KB ; B 320 rows x 64B = 20KB
#define SA   0
#define SB   4096
#define STG  24576
#define SMEM_TOTAL (2 * STG)

__device__ float g_h[(size_t)BT * NCOLS];
__device__ __half g_bh[(size_t)NCOLS * DDIM];

__device__ __forceinline__ uint32_t smem_u32(const void* p) {
    uint32_t a;
    asm("{ .reg .u64 t; cvta.to.shared.u64 t, %1; cvt.u32.u64 %0, t; }" : "=r"(a) : "l"(p));
    return a;
}
__device__ __forceinline__ uint32_t swz(int row, int u) {
    return (uint32_t)(row * 64 + ((u ^ ((row >> 1) & 3)) << 4));
}
__device__ __forceinline__ void st4(uint32_t a, uint32_t x, uint32_t y, uint32_t z, uint32_t w) {
    asm volatile("st.shared.v4.b32 [%0], {%1,%2,%3,%4};" :: "r"(a), "r"(x), "r"(y), "r"(z), "r"(w));
}
__device__ __forceinline__ void cpa16(uint32_t dst, const void* src) {
    asm volatile("cp.async.cg.shared.global [%0], [%1], 16;"
        :: "r"(dst), "l"((size_t)__cvta_generic_to_global(src)) : "memory");
}
#define CP_COMMIT() asm volatile("cp.async.commit_group;" ::: "memory")
#define CP_WAIT1()  asm volatile("cp.async.wait_group 1;" ::: "memory")

#define LDM4(r, a) \
    asm volatile("ldmatrix.sync.aligned.m8n8.x4.shared.b16 {%0,%1,%2,%3}, [%4];" \
        : "=r"((r)[0]), "=r"((r)[1]), "=r"((r)[2]), "=r"((r)[3]) : "r"(a))

#define MMA(c, a, b) \
    asm volatile("mma.sync.aligned.m16n8k16.row.col.f32.f16.f16.f32 " \
        "{%0,%1,%2,%3},{%4,%5,%6,%7},{%8,%9},{%0,%1,%2,%3};" \
        : "+f"((c)[0]), "+f"((c)[1]), "+f"((c)[2]), "+f"((c)[3]) \
        : "r"((a)[0]), "r"((a)[1]), "r"((a)[2]), "r"((a)[3]), "r"((b)[0]), "r"((b)[1]))

// ---- kernel 1: pack selected W columns (x64) into fp16 ----
__global__ void pack_b_kernel(const float* __restrict__ dw1, const float* __restrict__ dd) {
    int idx = blockIdx.x * blockDim.x + threadIdx.x;
    if (idx >= NCOLS * DDIM) return;
    int n = idx / DDIM, k = idx % DDIM;
    float v;
    if (n < 128)      v = dw1[k * 512 + n];
    else if (n < 256) v = dw1[k * 512 + 256 + (n - 128)];
    else if (n < 288) v = dd[k * 128 + (n - 256)];
    else              v = dd[k * 128 + 64 + (n - 288)];
    g_bh[idx] = __float2half_rn(v * BSCALE);
}

// ---- kernel 2: fp16 HMMA GEMM, BM=64, 16 warps (warp tile 16x80), no spills ----
__global__ void __launch_bounds__(512, 1) gemm_hmma(const float* __restrict__ Q) {
    extern __shared__ __align__(1024) unsigned char sm[];
    const uint32_t sb = smem_u32(sm);
    const int tid = threadIdx.x, lane = tid & 31, wid = tid >> 5;
    const int wm = wid & 3, wn = wid >> 2;   // 4 M-warps (16 rows) x 4 N-warps (80 cols)
    const int m0 = blockIdx.x * BM;

    // A convert mapping: 64 rows x 4 units = 256 slots; threads 256+ idle for A
    const bool a_on = (tid < 256);
    const int arow = tid >> 2, au = tid & 3;
    const float* aptr = Q + (size_t)(m0 + (a_on ? arow : 0)) * DDIM + au * 8;
    const uint32_t a_dst = SA + swz(arow & 63, au);

    // B cp.async mapping: 1280 16B-units over 512 threads (2.5/thread, guarded)
    const __half* bsrc[3];
    uint32_t bdst[3];
    bool bok[3];
#pragma unroll
    for (int j = 0; j < 3; j++) {
        int idx = tid + j * 512;
        bok[j] = (idx < NCOLS * 4);
        int row = bok[j] ? (idx >> 2) : 0;
        int u = idx & 3;
        bsrc[j] = g_bh + (size_t)row * DDIM + u * 8;
        bdst[j] = SB + swz(row, u);
    }

    // ldmatrix address precompute
    const int la = lane >> 4;
    const int lb = (lane >> 3) & 1;
    uint32_t a_r64; int a_rsw;
    {
        int ra = wm * 16 + (lane & 15);
        a_r64 = ra * 64; a_rsw = (ra >> 1) & 3;
    }
    uint32_t b_r64[5]; int b_rsw[5];
#pragma unroll
    for (int t = 0; t < 5; t++) {
        int rb = wn * 80 + t * 16 + ((lane >> 4) & 1) * 8 + (lane & 7);
        b_r64[t] = rb * 64; b_rsw[t] = (rb >> 1) & 3;
    }

    float4 ra0, ra1;
    float acc[10][4];
#pragma unroll
    for (int j = 0; j < 10; j++)
#pragma unroll
        for (int v = 0; v < 4; v++) acc[j][v] = 0.0f;

#define LDGA(i) do { if (a_on) { const float4* _p = (const float4*)(aptr + (size_t)(i) * BK); \
    ra0 = __ldg(_p); ra1 = __ldg(_p + 1); } } while (0)

#define STSA(stg) do { if (a_on) { \
    __half2 c0 = __floats2half2_rn(ra0.x, ra0.y); \
    __half2 c1 = __floats2half2_rn(ra0.z, ra0.w); \
    __half2 c2 = __floats2half2_rn(ra1.x, ra1.y); \
    __half2 c3 = __floats2half2_rn(ra1.z, ra1.w); \
    st4((stg) + a_dst, *(uint32_t*)&c0, *(uint32_t*)&c1, *(uint32_t*)&c2, *(uint32_t*)&c3); } } while (0)

#define CPB(i, stg) do { \
    _Pragma("unroll") \
    for (int _j = 0; _j < 3; _j++) \
        if (bok[_j]) cpa16((stg) + bdst[_j], bsrc[_j] + (size_t)(i) * BK); } while (0)

    // prologue
    LDGA(0); CPB(0, sb); CP_COMMIT();
    STSA(sb);
    LDGA(1); CPB(1, sb + STG); CP_COMMIT();
    CP_WAIT1();
    __syncthreads();

    for (int i = 0; i < KIT; i++) {
        const uint32_t sbase = sb + (i & 1) * STG;
#pragma unroll
        for (int kk = 0; kk < 2; kk++) {
            uint32_t ah[4];
            {
                uint32_t auo = (uint32_t)((((kk << 1) + la) ^ a_rsw) << 4);
                LDM4(ah, sbase + SA + a_r64 + auo);
            }
#pragma unroll
            for (int t5 = 0; t5 < 5; t5++) {
                uint32_t buo = (uint32_t)((((kk << 1) + lb) ^ b_rsw[t5]) << 4);
                uint32_t bh4[4];
                LDM4(bh4, sbase + SB + b_r64[t5] + buo);
#pragma unroll
                for (int s = 0; s < 2; s++)
                    MMA(acc[t5 * 2 + s], ah, &bh4[s * 2]);
            }
        }
        __syncthreads();
        if (i + 1 < KIT) STSA(sb + ((i + 1) & 1) * STG);
        if (i + 2 < KIT) { LDGA(i + 2); CPB(i + 2, sbase); }
        CP_COMMIT();
        CP_WAIT1();
        __syncthreads();
    }

    // store H (scaled by BSCALE)
    {
        int row = m0 + wm * 16 + (lane >> 2);
#pragma unroll
        for (int nt = 0; nt < 10; nt++) {
            int col = wn * 80 + nt * 8 + (lane & 3) * 2;
            *(float2*)&g_h[(size_t)row * NCOLS + col] = make_float2(acc[nt][0], acc[nt][1]);
            *(float2*)&g_h[(size_t)(row + 8) * NCOLS + col] = make_float2(acc[nt][2], acc[nt][3]);
        }
    }
}

// ---- kernel 3: per-token epilogue (f32x2 packed FMA) ----
__global__ __launch_bounds__(256) void epilogue_kernel(const float* __restrict__ qkw,
                                                       const float* __restrict__ norm_scale,
                                                       float* __restrict__ out) {
    const int lane = threadIdx.x & 31, w = threadIdx.x >> 5;
    const int tok = blockIdx.x * 8 + w;
    if (tok >= BT) return;
    const float* h = g_h + (size_t)tok * NCOLS;
    float* o = out + (size_t)tok * NCOLS;
    const float scale = norm_scale[0];
    const int ii = lane >> 3, m4 = (lane & 7) * 4;

    __shared__ float hg[8][256];
#pragma unroll
    for (int p = 0; p < 8; p++) {
        float x = h[lane + p * 32] * INVBS;
        hg[w][lane + p * 32] = 0.5f * x * (1.0f + erff(x * 0.70710678118654752f));
    }
    o[128 + lane] = tanhf(h[256 + lane] * INVBS);
    o[288 + lane] = tanhf(h[288 + lane] * INVBS);
    __syncwarp();

#pragma unroll
    for (int cc = 0; cc < 2; cc++) {
        const float* qc = qkw + (size_t)(cc * 2) * 16384 + ii * 32 + m4;
        const float* hh = &hg[w][cc * 128];
        uint64_t acc01 = 0ull, acc23 = 0ull;
#pragma unroll 4
        for (int k = 0; k < 128; k++) {
            float hk = hh[k];
            uint64_t hk2;
            asm("mov.b64 %0, {%1, %1};" : "=l"(hk2) : "f"(hk));
            ulonglong2 wv = *(const ulonglong2*)(qc + (size_t)k * 128);
            asm("fma.rn.f32x2 %0, %1, %2, %0;" : "+l"(acc01) : "l"(hk2), "l"(wv.x));
            asm("fma.rn.f32x2 %0, %1, %2, %0;" : "+l"(acc23) : "l"(hk2), "l"(wv.y));
        }
        float a0, a1, a2, a3;
        asm("mov.b64 {%0, %1}, %2;" : "=f"(a0), "=f"(a1) : "l"(acc01));
        asm("mov.b64 {%0, %1}, %2;" : "=f"(a2), "=f"(a3) : "l"(acc23));
        float ss = a0 * a0 + a1 * a1 + a2 * a2 + a3 * a3;
#pragma unroll
        for (int m = 1; m < 8; m <<= 1) ss += __shfl_xor_sync(0xFFFFFFFFu, ss, m);
        float r = rsqrtf(ss * (1.0f / 32.0f) + EPSF);
        if (ii >= 2) r *= scale;
        *(float4*)&o[cc * 160 + ii * 32 + m4] = make_float4(a0 * r, a1 * r, a2 * r, a3 * r);
    }
}

extern "C" void kernel_launch(void* const* d_in, const int* in_sizes, int n_in,
                              void* d_out, int out_size) {
    const float* q   = (const float*)d_in[0];
    const float* dw1 = (const float*)d_in[1];
    const float* qkw = (const float*)d_in[2];
    const float* dd  = (const float*)d_in[3];
    const float* nsc = (const float*)d_in[4];
    float* out = (float*)d_out;

    cudaFuncSetAttribute(gemm_hmma, cudaFuncAttributeMaxDynamicSharedMemorySize, SMEM_TOTAL);
    pack_b_kernel<<<(NCOLS * DDIM + 255) / 256, 256>>>(dw1, dd);
    gemm_hmma<<<BT / BM, 512, SMEM_TOTAL>>>(q);
    epilogue_kernel<<<BT / 8, 256>>>(qkw, nsc, out);
}

// round 14
// speedup vs baseline: 1.2760x; 1.2760x over previous
#include <cuda_runtime.h>
#include <cuda_fp16.h>
#include <math.h>
#include <stdint.h>

#define BT    16384
#define DDIM  4096
#define NCOLS 320
#define EPSF  1.1920929e-07f
#define BSCALE 64.0f
#define INVBS  0.015625f

#define BM  128
#define BK  32
#define KIT (DDIM / BK)

// smem per stage: A 128 rows x 64B (fp16) = 8KB ; B 320 rows x 64B = 20KB
#define SA   0
#define SB   8192
#define STG  28672
#define NST  3
#define SMEM_TOTAL (NST * STG)   // 86016

__device__ float g_h[(size_t)BT * NCOLS];
__device__ __half g_bh[(size_t)NCOLS * DDIM];

__device__ __forceinline__ uint32_t smem_u32(const void* p) {
    uint32_t a;
    asm("{ .reg .u64 t; cvta.to.shared.u64 t, %1; cvt.u32.u64 %0, t; }" : "=r"(a) : "l"(p));
    return a;
}
__device__ __forceinline__ uint32_t swz(int row, int u) {
    return (uint32_t)(row * 64 + ((u ^ ((row >> 1) & 3)) << 4));
}
__device__ __forceinline__ void st4(uint32_t a, uint32_t x, uint32_t y, uint32_t z, uint32_t w) {
    asm volatile("st.shared.v4.b32 [%0], {%1,%2,%3,%4};" :: "r"(a), "r"(x), "r"(y), "r"(z), "r"(w));
}
__device__ __forceinline__ void cpa16(uint32_t dst, const void* src) {
    asm volatile("cp.async.cg.shared.global [%0], [%1], 16;"
        :: "r"(dst), "l"((size_t)__cvta_generic_to_global(src)) : "memory");
}
#define CP_COMMIT() asm volatile("cp.async.commit_group;" ::: "memory")
#define CP_WAIT2()  asm volatile("cp.async.wait_group 2;" ::: "memory")

#define LDM4(r, a) \
    asm volatile("ldmatrix.sync.aligned.m8n8.x4.shared.b16 {%0,%1,%2,%3}, [%4];" \
        : "=r"((r)[0]), "=r"((r)[1]), "=r"((r)[2]), "=r"((r)[3]) : "r"(a))

#define MMA(c, a, b) \
    asm volatile("mma.sync.aligned.m16n8k16.row.col.f32.f16.f16.f32 " \
        "{%0,%1,%2,%3},{%4,%5,%6,%7},{%8,%9},{%0,%1,%2,%3};" \
        : "+f"((c)[0]), "+f"((c)[1]), "+f"((c)[2]), "+f"((c)[3]) \
        : "r"((a)[0]), "r"((a)[1]), "r"((a)[2]), "r"((a)[3]), "r"((b)[0]), "r"((b)[1]))

// ---- kernel 1: pack selected W columns (x64) into fp16 ----
__global__ void pack_b_kernel(const float* __restrict__ dw1, const float* __restrict__ dd) {
    int idx = blockIdx.x * blockDim.x + threadIdx.x;
    if (idx >= NCOLS * DDIM) return;
    int n = idx / DDIM, k = idx % DDIM;
    float v;
    if (n < 128)      v = dw1[k * 512 + n];
    else if (n < 256) v = dw1[k * 512 + 256 + (n - 128)];
    else if (n < 288) v = dd[k * 128 + (n - 256)];
    else              v = dd[k * 128 + 64 + (n - 288)];
    g_bh[idx] = __float2half_rn(v * BSCALE);
}

// ---- kernel 2: fp16 HMMA GEMM, 3-stage ring, ONE barrier/iter ----
__global__ void __launch_bounds__(512, 1) gemm_hmma(const float* __restrict__ Q) {
    extern __shared__ __align__(1024) unsigned char sm[];
    const uint32_t sb = smem_u32(sm);
    const int tid = threadIdx.x, lane = tid & 31, wid = tid >> 5;
    const int wm = wid & 3, wn = wid >> 2;
    const int m0 = blockIdx.x * BM;

    // A convert mapping: thread -> (row = tid>>2, 8 consecutive k at (tid&3)*8)
    const int arow = tid >> 2, au = tid & 3;
    const float* aptr = Q + (size_t)(m0 + arow) * DDIM + au * 8;
    const uint32_t a_dst = SA + swz(arow, au);

    // B cp.async mapping: 1280 16B-units over 512 threads (2 each + 256 extra)
    const __half* bsrc[3];
    uint32_t bdst[3];
    const bool b3 = (tid < 256);
#pragma unroll
    for (int j = 0; j < 3; j++) {
        int idx = tid + j * 512;
        int row = (j < 2 || b3) ? (idx >> 2) : 0;
        int u = idx & 3;
        bsrc[j] = g_bh + (size_t)row * DDIM + u * 8;
        bdst[j] = SB + swz(row, u);
    }

    // ldmatrix address precompute
    const int la = lane >> 4;
    const int lb = (lane >> 3) & 1;
    uint32_t a_r64[2]; int a_rsw[2];
#pragma unroll
    for (int t = 0; t < 2; t++) {
        int ra = wm * 32 + (lane & 15) + t * 16;
        a_r64[t] = ra * 64; a_rsw[t] = (ra >> 1) & 3;
    }
    uint32_t b_r64[5]; int b_rsw[5];
#pragma unroll
    for (int t = 0; t < 5; t++) {
        int rb = wn * 80 + t * 16 + ((lane >> 4) & 1) * 8 + (lane & 7);
        b_r64[t] = rb * 64; b_rsw[t] = (rb >> 1) & 3;
    }

    float4 ra0, ra1;
    float acc[2][10][4];
#pragma unroll
    for (int i = 0; i < 2; i++)
#pragma unroll
        for (int j = 0; j < 10; j++)
#pragma unroll
            for (int v = 0; v < 4; v++) acc[i][j][v] = 0.0f;

#define LDGA(i) do { const float4* _p = (const float4*)(aptr + (size_t)(i) * BK); \
    ra0 = __ldg(_p); ra1 = __ldg(_p + 1); } while (0)

#define STSA(stg) do { \
    __half2 c0 = __floats2half2_rn(ra0.x, ra0.y); \
    __half2 c1 = __floats2half2_rn(ra0.z, ra0.w); \
    __half2 c2 = __floats2half2_rn(ra1.x, ra1.y); \
    __half2 c3 = __floats2half2_rn(ra1.z, ra1.w); \
    st4((stg) + a_dst, *(uint32_t*)&c0, *(uint32_t*)&c1, *(uint32_t*)&c2, *(uint32_t*)&c3); } while (0)

#define CPB(i, stg) do { \
    cpa16((stg) + bdst[0], bsrc[0] + (size_t)(i) * BK); \
    cpa16((stg) + bdst[1], bsrc[1] + (size_t)(i) * BK); \
    if (b3) cpa16((stg) + bdst[2], bsrc[2] + (size_t)(i) * BK); } while (0)

    // prologue: B groups g0,g1 in flight; A(0) stored; A(1) in regs
    LDGA(0);
    CPB(0, sb); CP_COMMIT();
    CPB(1, sb + STG); CP_COMMIT();
    STSA(sb);
    LDGA(1);
    __syncthreads();

    for (int i = 0; i < KIT; i++) {
        const uint32_t scur = sb + (i % 3) * STG;
        // issue B(i+2) into stage (i+2)%3 (readers finished at iter i-1)
        if (i + 2 < KIT) CPB(i + 2, sb + ((i + 2) % 3) * STG);
        CP_COMMIT();
        CP_WAIT2();   // group i complete (issued 2 iters ago)

#pragma unroll
        for (int kk = 0; kk < 2; kk++) {
            uint32_t ah[2][4];
#pragma unroll
            for (int t = 0; t < 2; t++) {
                uint32_t auo = (uint32_t)((((kk << 1) + la) ^ a_rsw[t]) << 4);
                LDM4(ah[t], scur + SA + a_r64[t] + auo);
            }
#pragma unroll
            for (int t5 = 0; t5 < 5; t5++) {
                uint32_t buo = (uint32_t)((((kk << 1) + lb) ^ b_rsw[t5]) << 4);
                uint32_t bh4[4];
                LDM4(bh4, scur + SB + b_r64[t5] + buo);
#pragma unroll
                for (int mt = 0; mt < 2; mt++)
#pragma unroll
                    for (int s = 0; s < 2; s++)
                        MMA(acc[mt][t5 * 2 + s], ah[mt], &bh4[s * 2]);
            }
        }

        // A(i+1) -> stage (i+1)%3 (untouched since iter i-2); refill regs
        if (i + 1 < KIT) STSA(sb + ((i + 1) % 3) * STG);
        if (i + 2 < KIT) LDGA(i + 2);
        __syncthreads();
    }

    // store H (scaled by BSCALE)
#pragma unroll
    for (int mt = 0; mt < 2; mt++) {
        int row = m0 + wm * 32 + mt * 16 + (lane >> 2);
#pragma unroll
        for (int nt = 0; nt < 10; nt++) {
            int col = wn * 80 + nt * 8 + (lane & 3) * 2;
            *(float2*)&g_h[(size_t)row * NCOLS + col] =
                make_float2(acc[mt][nt][0], acc[mt][nt][1]);
            *(float2*)&g_h[(size_t)(row + 8) * NCOLS + col] =
                make_float2(acc[mt][nt][2], acc[mt][nt][3]);
        }
    }
}

// ---- kernel 3: per-token epilogue (f32x2 packed FMA) ----
__global__ __launch_bounds__(256) void epilogue_kernel(const float* __restrict__ qkw,
                                                       const float* __restrict__ norm_scale,
                                                       float* __restrict__ out) {
    const int lane = threadIdx.x & 31, w = threadIdx.x >> 5;
    const int tok = blockIdx.x * 8 + w;
    if (tok >= BT) return;
    const float* h = g_h + (size_t)tok * NCOLS;
    float* o = out + (size_t)tok * NCOLS;
    const float scale = norm_scale[0];
    const int ii = lane >> 3, m4 = (lane & 7) * 4;

    __shared__ float hg[8][256];
#pragma unroll
    for (int p = 0; p < 8; p++) {
        float x = h[lane + p * 32] * INVBS;
        hg[w][lane + p * 32] = 0.5f * x * (1.0f + erff(x * 0.70710678118654752f));
    }
    o[128 + lane] = tanhf(h[256 + lane] * INVBS);
    o[288 + lane] = tanhf(h[288 + lane] * INVBS);
    __syncwarp();

#pragma unroll
    for (int cc = 0; cc < 2; cc++) {
        const float* qc = qkw + (size_t)(cc * 2) * 16384 + ii * 32 + m4;
        const float* hh = &hg[w][cc * 128];
        uint64_t acc01 = 0ull, acc23 = 0ull;
#pragma unroll 4
        for (int k = 0; k < 128; k++) {
            float hk = hh[k];
            uint64_t hk2;
            asm("mov.b64 %0, {%1, %1};" : "=l"(hk2) : "f"(hk));
            ulonglong2 wv = *(const ulonglong2*)(qc + (size_t)k * 128);
            asm("fma.rn.f32x2 %0, %1, %2, %0;" : "+l"(acc01) : "l"(hk2), "l"(wv.x));
            asm("fma.rn.f32x2 %0, %1, %2, %0;" : "+l"(acc23) : "l"(hk2), "l"(wv.y));
        }
        float a0, a1, a2, a3;
        asm("mov.b64 {%0, %1}, %2;" : "=f"(a0), "=f"(a1) : "l"(acc01));
        asm("mov.b64 {%0, %1}, %2;" : "=f"(a2), "=f"(a3) : "l"(acc23));
        float ss = a0 * a0 + a1 * a1 + a2 * a2 + a3 * a3;
#pragma unroll
        for (int m = 1; m < 8; m <<= 1) ss += __shfl_xor_sync(0xFFFFFFFFu, ss, m);
        float r = rsqrtf(ss * (1.0f / 32.0f) + EPSF);
        if (ii >= 2) r *= scale;
        *(float4*)&o[cc * 160 + ii * 32 + m4] = make_float4(a0 * r, a1 * r, a2 * r, a3 * r);
    }
}

extern "C" void kernel_launch(void* const* d_in, const int* in_sizes, int n_in,
                              void* d_out, int out_size) {
    const float* q   = (const float*)d_in[0];
    const float* dw1 = (const float*)d_in[1];
    const float* qkw = (const float*)d_in[2];
    const float* dd  = (const float*)d_in[3];
    const float* nsc = (const float*)d_in[4];
    float* out = (float*)d_out;

    cudaFuncSetAttribute(gemm_hmma, cudaFuncAttributeMaxDynamicSharedMemorySize, SMEM_TOTAL);
    pack_b_kernel<<<(NCOLS * DDIM + 255) / 256, 256>>>(dw1, dd);
    gemm_hmma<<<BT / BM, 512, SMEM_TOTAL>>>(q);
    epilogue_kernel<<<BT / 8, 256>>>(qkw, nsc, out);
}